// round 8
// baseline (speedup 1.0000x reference)
#include <cuda_runtime.h>
#include <cuda_fp16.h>
#include <cstdint>

// DepthConv: out[b,o,p] = sum_t gate[b,t,p] * sum_c w[t,o,c]*x[b,c,p+shift(t)]
// Epoch-major halo (staged once per epoch); taps processed in GROUPS of 3
// (one kernel row) between barriers. B staged as 3-tap blocks, double-buffered
// one group ahead. B fragments preloaded per tap; A fragments pipelined one
// ks ahead; gate applied to A fragments in fp16 (HMUL2).

#define ALPHA_F 8.3f

constexpr int Bn = 8;
constexpr int Cn = 512;
constexpr int Hn = 64;
constexpr int Wn = 64;
constexpr int On = 64;
constexpr int PIXn = Hn * Wn;       // 4096

constexpr int Mt = 128;             // pixels per CTA (8 rows x 16 cols)
constexpr int KC = 64;              // c-chunk per epoch
constexpr int EPOCHS = Cn / KC;     // 8
constexpr int GPE = 3;              // tap-groups per epoch (one kernel row each)
constexpr int NG = EPOCHS * GPE;    // 24 groups
constexpr int HE = 180;             // halo entries (10 x 18)
constexpr int HS = 72;              // smem row stride in halves (64 + 8 pad)

// ---- device-global scratch ----
__device__ __half g_xh[(size_t)Bn * PIXn * Cn];   // [b][pixel][c] fp16
__device__ __half g_wh[9 * On * Cn];              // [tap][o][c]  fp16

// ---- smem layout (bytes) ----
constexpr int HBUF  = HE * HS * 2;           // 25920 (x2)
constexpr int BTAP  = On * HS * 2;           // 9216 per tap
constexpr int BGBUF = 3 * BTAP;              // 27648 per group (x2)
constexpr int OFF_H = 0;
constexpr int OFF_B = 2 * HBUF;              // 51840
constexpr int OFF_G = OFF_B + 2 * BGBUF;     // 107136 gates 9*128*4
constexpr int SMEM_TOTAL = OFF_G + 9 * Mt * 4;  // 111744 -> 2 CTAs/SM

// ====================== helpers ======================
__device__ __forceinline__ uint32_t smem_u32(const void* p) {
    uint32_t a;
    asm("{ .reg .u64 t; cvta.to.shared.u64 t, %1; cvt.u32.u64 %0, t; }"
        : "=r"(a) : "l"(p));
    return a;
}
__device__ __forceinline__ void ldsm_x4(uint32_t* r, uint32_t addr) {
    asm volatile("ldmatrix.sync.aligned.m8n8.x4.shared.b16 {%0,%1,%2,%3}, [%4];"
        : "=r"(r[0]), "=r"(r[1]), "=r"(r[2]), "=r"(r[3]) : "r"(addr));
}
__device__ __forceinline__ void mma16816(float* c, const uint32_t* a,
                                         uint32_t b0, uint32_t b1) {
    asm volatile(
        "mma.sync.aligned.m16n8k16.row.col.f32.f16.f16.f32 "
        "{%0,%1,%2,%3}, {%4,%5,%6,%7}, {%8,%9}, {%0,%1,%2,%3};"
        : "+f"(c[0]), "+f"(c[1]), "+f"(c[2]), "+f"(c[3])
        : "r"(a[0]), "r"(a[1]), "r"(a[2]), "r"(a[3]), "r"(b0), "r"(b1));
}
__device__ __forceinline__ uint32_t hmul2u(uint32_t a, uint32_t g) {
    __half2 r = __hmul2(*reinterpret_cast<__half2*>(&a),
                        *reinterpret_cast<__half2*>(&g));
    return *reinterpret_cast<uint32_t*>(&r);
}
#define CP_ASYNC16(dst, src) \
    asm volatile("cp.async.cg.shared.global [%0], [%1], 16;" \
                 :: "r"(dst), "l"(src) : "memory")
#define CP_COMMIT() asm volatile("cp.async.commit_group;" ::: "memory")
#define CP_WAIT0()  asm volatile("cp.async.wait_group 0;" ::: "memory")

// ====================== fused pre-pass ======================
constexpr int NT_BLK = Bn * (Cn / 64) * (PIXn / 64);   // 4096
constexpr int NW_ELEM = 9 * On * Cn;                   // 294912
constexpr int NW_BLK = NW_ELEM / (256 * 8);            // 144

__global__ __launch_bounds__(256) void prep_all(const float* __restrict__ x,
                                                const float* __restrict__ w) {
    const int bi = blockIdx.x;
    if (bi < NT_BLK) {
        __shared__ float tile[64][65];
        const int b  = bi / ((Cn / 64) * (PIXn / 64));
        const int r  = bi % ((Cn / 64) * (PIXn / 64));
        const int c0 = (r / (PIXn / 64)) * 64;
        const int p0 = (r % (PIXn / 64)) * 64;
        const int lane = threadIdx.x & 31;
        const int wrp  = threadIdx.x >> 5;     // 0..7
        #pragma unroll
        for (int j = 0; j < 8; j++) {          // warp handles 8 c-rows
            const int c = wrp * 8 + j;
            const float2 v = *reinterpret_cast<const float2*>(
                &x[((size_t)(b * Cn + c0 + c)) * PIXn + p0 + lane * 2]);
            tile[c][lane * 2]     = v.x;
            tile[c][lane * 2 + 1] = v.y;
        }
        __syncthreads();
        #pragma unroll
        for (int j = 0; j < 8; j++) {          // warp handles 8 pixel-rows
            const int p = wrp * 8 + j;
            __half2 v = __floats2half2_rn(tile[lane * 2][p], tile[lane * 2 + 1][p]);
            *reinterpret_cast<__half2*>(
                &g_xh[((size_t)(b * PIXn + p0 + p)) * Cn + c0 + lane * 2]) = v;
        }
    } else {
        const int base = (bi - NT_BLK) * 2048 + threadIdx.x;
        #pragma unroll
        for (int j = 0; j < 8; j++) {
            const int idx = base + j * 256;          // [t][o][c]
            const int c = idx % Cn;
            const int o = (idx / Cn) % On;
            const int t = idx / (Cn * On);
            g_wh[idx] = __float2half_rn(w[((size_t)o * Cn + c) * 9 + t]);
        }
    }
}

// ====================== main kernel ======================
__global__ __launch_bounds__(256, 2) void depthconv_mma(
    const float* __restrict__ depth,
    float* __restrict__ out)
{
    extern __shared__ __align__(16) char smem[];
    const uint32_t sb = smem_u32(smem);
    uint32_t* g_sp = reinterpret_cast<uint32_t*>(smem + OFF_G);  // [9][128] half2

    const int tid = threadIdx.x;
    const int wid = tid >> 5;
    const int lid = tid & 31;

    const int blk = blockIdx.x;          // 0..255
    const int b   = blk >> 5;
    const int tl  = blk & 31;
    const int h0  = (tl >> 2) * 8;       // 8 pixel rows
    const int w0  = (tl & 3) * 16;       // 16 pixel cols

    // ---- gates: 9 taps x 128 pixels, stored as (g,g) half2 ----
    if (tid < Mt) {
        const int hh = h0 + (tid >> 4);
        const int ww = w0 + (tid & 15);
        const float* dptr = depth + b * PIXn;
        const float d0 = dptr[hh * Wn + ww];
        #pragma unroll
        for (int t = 0; t < 9; t++) {
            const int h2 = hh + t / 3 - 1, w2 = ww + t % 3 - 1;
            float g = 0.f;
            if (h2 >= 0 && h2 < Hn && w2 >= 0 && w2 < Wn)
                g = __expf(-ALPHA_F * fabsf(d0 - dptr[h2 * Wn + w2]));
            const __half gh = __float2half_rn(g);
            __half2 gp = __halves2half2(gh, gh);
            g_sp[t * Mt + tid] = *reinterpret_cast<uint32_t*>(&gp);
        }
    }

    // ---- halo staging slots (epoch-invariant addressing) ----
    const __half* xb = g_xh + (size_t)b * PIXn * Cn;
    const int nj = (tid < 160) ? 6 : 5;   // 1440 chunks over 256 threads
    int qoff[6];        // global half offset (add c0)
    uint32_t soff[6];   // smem byte offset within halo buffer
    #pragma unroll
    for (int j = 0; j < 6; j++) {
        const int i = tid + j * 256;
        const int ent = i >> 3, seg = i & 7;
        const int hr = ent / 18, hc = ent - hr * 18;
        const int hh = min(max(h0 - 1 + hr, 0), Hn - 1);
        const int ww = min(max(w0 - 1 + hc, 0), Wn - 1);
        qoff[j] = (hh * Wn + ww) * Cn + seg * 8;
        soff[j] = (uint32_t)(ent * HS + seg * 8) * 2;
    }
    // B staging: per tap 64 rows x 8 segs = 512 chunks -> 2 per thread
    uint32_t bsoff[2];
    int boff[2];
    #pragma unroll
    for (int j = 0; j < 2; j++) {
        const int i = tid + j * 256;
        const int o = i >> 3, seg = i & 7;
        boff[j]  = o * Cn + seg * 8;              // add tap*On*Cn + c0
        bsoff[j] = (uint32_t)(o * HS + seg * 8) * 2;
    }

    auto stage_halo = [&](int e, int buf) {
        const int c0 = e * KC;
        const uint32_t hd = sb + OFF_H + buf * HBUF;
        #pragma unroll
        for (int j = 0; j < 6; j++)
            if (j < nj)
                CP_ASYNC16(hd + soff[j], (const char*)(xb + qoff[j] + c0));
    };
    auto stage_Bg = [&](int g, int buf) {      // 3 taps of group g
        const int e = g / GPE, t0 = (g % GPE) * 3;
        const uint32_t bd = sb + OFF_B + buf * BGBUF;
        const __half* wsrc = g_wh + e * KC;
        #pragma unroll
        for (int tt = 0; tt < 3; tt++) {
            const __half* ws = wsrc + (size_t)(t0 + tt) * On * Cn;
            #pragma unroll
            for (int j = 0; j < 2; j++)
                CP_ASYNC16(bd + tt * BTAP + bsoff[j], (const char*)(ws + boff[j]));
        }
    };

    // ---- warp tiling: 4 (m) x 2 (n) warps; warp tile 32x32 ----
    const int wm = (wid & 3) * 32;
    const int wn = (wid >> 2) * 32;

    uint32_t abase[2];                    // per-lane A ldmatrix base (tap 0)
    #pragma unroll
    for (int mb = 0; mb < 2; mb++) {
        const int m   = wm + mb * 16 + (lid & 15);
        const int ent = (m >> 4) * 18 + (m & 15);
        abase[mb] = sb + OFF_H + (uint32_t)(ent * HS) * 2 + (uint32_t)(lid >> 4) * 16;
    }
    uint32_t bbase[2];                    // per-lane B ldmatrix base
    {
        const int br = (lid & 7) + ((lid >> 4) << 3);
        const uint32_t bcol = (uint32_t)(((lid >> 3) & 1) << 3) * 2;
        #pragma unroll
        for (int np = 0; np < 2; np++)
            bbase[np] = sb + OFF_B + (uint32_t)((wn + np * 16 + br) * HS) * 2 + bcol;
    }
    const int grow = (lid >> 2);          // gate row within warp m-block

    float facc[2][4][4];
    #pragma unroll
    for (int i = 0; i < 2; i++)
        #pragma unroll
        for (int j = 0; j < 4; j++)
            #pragma unroll
            for (int k = 0; k < 4; k++) facc[i][j][k] = 0.f;

    // prologue: halo(epoch 0) + B(group 0)
    stage_halo(0, 0);
    stage_Bg(0, 0);
    CP_COMMIT();

    for (int g = 0; g < NG; g++) {
        const int e    = g / GPE;
        const int trow = g % GPE;          // group = one kernel row of taps

        CP_WAIT0();
        __syncthreads();    // group-g data (and, first group, gates) visible

        // stage next group right after the barrier (overlaps with compute)
        if (g + 1 < NG) {
            stage_Bg(g + 1, (g + 1) & 1);
            if (((g + 1) % GPE) == 0)          // next group starts epoch e+1
                stage_halo(e + 1, (e + 1) & 1);
            CP_COMMIT();
        }

        const uint32_t hbufo = (uint32_t)(e & 1) * HBUF;
        const uint32_t bgo   = (uint32_t)(g & 1) * BGBUF;

        #pragma unroll
        for (int tt = 0; tt < 3; tt++) {       // taps: trow*3 + tt
            const int t = trow * 3 + tt;
            const uint32_t aoff = hbufo + (uint32_t)((trow * 18 + tt) * (HS * 2));
            const uint32_t boffb = bgo + (uint32_t)(tt * BTAP);

            uint32_t g0[2], g1[2];             // (g,g) half2 per fragment row
            #pragma unroll
            for (int mb = 0; mb < 2; mb++) {
                const int r = wm + mb * 16 + grow;
                g0[mb] = g_sp[t * Mt + r];
                g1[mb] = g_sp[t * Mt + r + 8];
            }

            // preload all B fragments for this tap (8 ldsm, 32 regs)
            uint32_t bfr[4][2][4];
            #pragma unroll
            for (int ks = 0; ks < 4; ks++)
                #pragma unroll
                for (int np = 0; np < 2; np++)
                    ldsm_x4(bfr[ks][np], bbase[np] + boffb + ks * 32);

            // A pipelined one ks ahead
            uint32_t af[2][2][4];              // [pipe buf][mb][4]
            #pragma unroll
            for (int mb = 0; mb < 2; mb++)
                ldsm_x4(af[0][mb], abase[mb] + aoff);

            #pragma unroll
            for (int ks = 0; ks < 4; ks++) {
                const int cur = ks & 1, nxt = cur ^ 1;
                if (ks < 3)
                    #pragma unroll
                    for (int mb = 0; mb < 2; mb++)
                        ldsm_x4(af[nxt][mb], abase[mb] + aoff + (ks + 1) * 32);
                uint32_t ag[2][4];
                #pragma unroll
                for (int mb = 0; mb < 2; mb++) {
                    ag[mb][0] = hmul2u(af[cur][mb][0], g0[mb]);
                    ag[mb][1] = hmul2u(af[cur][mb][1], g1[mb]);
                    ag[mb][2] = hmul2u(af[cur][mb][2], g0[mb]);
                    ag[mb][3] = hmul2u(af[cur][mb][3], g1[mb]);
                }
                #pragma unroll
                for (int mb = 0; mb < 2; mb++)
                    #pragma unroll
                    for (int nb = 0; nb < 4; nb++)
                        mma16816(facc[mb][nb], ag[mb],
                                 bfr[ks][nb >> 1][(nb & 1) * 2],
                                 bfr[ks][nb >> 1][(nb & 1) * 2 + 1]);
            }
        }
    }

    // ---- epilogue: D(m=pixel, n=o) -> out[b][o][h][w] ----
    float* ob = out + (size_t)b * On * PIXn;
    const int mrow = wm + (lid >> 2);
    const int ncol = wn + (lid & 3) * 2;
    #pragma unroll
    for (int mb = 0; mb < 2; mb++) {
        #pragma unroll
        for (int half_ = 0; half_ < 2; half_++) {
            const int m  = mrow + mb * 16 + half_ * 8;
            const int hh = h0 + (m >> 4);
            const int ww = w0 + (m & 15);
            const int pix = hh * Wn + ww;
            #pragma unroll
            for (int nb = 0; nb < 4; nb++) {
                const int o = ncol + nb * 8;
                ob[(size_t)o * PIXn + pix]       = facc[mb][nb][half_ * 2];
                ob[(size_t)(o + 1) * PIXn + pix] = facc[mb][nb][half_ * 2 + 1];
            }
        }
    }
}

// ====================== launch ======================
extern "C" void kernel_launch(void* const* d_in, const int* in_sizes, int n_in,
                              void* d_out, int out_size) {
    const float* x     = (const float*)d_in[0];   // (8,512,64,64)
    const float* depth = (const float*)d_in[1];   // (8,1,64,64)
    const float* w     = (const float*)d_in[2];   // (64,512,3,3)
    float* out = (float*)d_out;                   // (8,64,64,64)

    cudaFuncSetAttribute(depthconv_mma,
                         cudaFuncAttributeMaxDynamicSharedMemorySize,
                         SMEM_TOTAL);

    prep_all<<<NT_BLK + NW_BLK, 256>>>(x, w);
    depthconv_mma<<<Bn * 32, 256, SMEM_TOTAL>>>(depth, out);
}

// round 9
// speedup vs baseline: 1.0140x; 1.0140x over previous
#include <cuda_runtime.h>
#include <cuda_fp16.h>
#include <cstdint>

// DepthConv: out[b,o,p] = sum_t gate[b,t,p] * sum_c w[t,o,c]*x[b,c,p+shift(t)]
// Round-7 pipeline (per-tap spread staging, 3-buffer B, wait1) with 128
// threads / 4 warps per CTA and 64x32 warp tiles: halves smem-read bytes
// per MMA (187B/mma), putting the kernel on the tensor pipe, not the
// smem crossbar. Gate applied to A fragments in fp16 (HMUL2).

#define ALPHA_F 8.3f

constexpr int Bn = 8;
constexpr int Cn = 512;
constexpr int Hn = 64;
constexpr int Wn = 64;
constexpr int On = 64;
constexpr int PIXn = Hn * Wn;       // 4096

constexpr int Mt = 128;             // pixels per CTA (8 rows x 16 cols)
constexpr int KC = 64;              // c-chunk per epoch
constexpr int EPOCHS = Cn / KC;     // 8
constexpr int NIT = EPOCHS * 9;     // 72 (epoch-major, tap-minor)
constexpr int HE = 180;             // halo entries (10 x 18)
constexpr int HS = 72;              // smem row stride in halves (64 + 8 pad)
constexpr int NTHR = 128;           // 4 warps

// ---- device-global scratch ----
__device__ __half g_xh[(size_t)Bn * PIXn * Cn];   // [b][pixel][c] fp16
__device__ __half g_wh[9 * On * Cn];              // [tap][o][c]  fp16

// ---- smem layout (bytes) ----
constexpr int HBUF = HE * HS * 2;            // 25920 (x2 buffers)
constexpr int BBUF = On * HS * 2;            // 9216  (x3 buffers)
constexpr int OFF_H = 0;
constexpr int OFF_B = 2 * HBUF;              // 51840
constexpr int OFF_G = OFF_B + 3 * BBUF;      // 79488 gates 9*128*4
constexpr int SMEM_TOTAL = OFF_G + 9 * Mt * 4;  // 84096 -> 2 CTAs/SM

// ====================== helpers ======================
__device__ __forceinline__ uint32_t smem_u32(const void* p) {
    uint32_t a;
    asm("{ .reg .u64 t; cvta.to.shared.u64 t, %1; cvt.u32.u64 %0, t; }"
        : "=r"(a) : "l"(p));
    return a;
}
__device__ __forceinline__ void ldsm_x4(uint32_t* r, uint32_t addr) {
    asm volatile("ldmatrix.sync.aligned.m8n8.x4.shared.b16 {%0,%1,%2,%3}, [%4];"
        : "=r"(r[0]), "=r"(r[1]), "=r"(r[2]), "=r"(r[3]) : "r"(addr));
}
__device__ __forceinline__ void mma16816(float* c, const uint32_t* a,
                                         uint32_t b0, uint32_t b1) {
    asm volatile(
        "mma.sync.aligned.m16n8k16.row.col.f32.f16.f16.f32 "
        "{%0,%1,%2,%3}, {%4,%5,%6,%7}, {%8,%9}, {%0,%1,%2,%3};"
        : "+f"(c[0]), "+f"(c[1]), "+f"(c[2]), "+f"(c[3])
        : "r"(a[0]), "r"(a[1]), "r"(a[2]), "r"(a[3]), "r"(b0), "r"(b1));
}
__device__ __forceinline__ uint32_t hmul2u(uint32_t a, uint32_t g) {
    __half2 r = __hmul2(*reinterpret_cast<__half2*>(&a),
                        *reinterpret_cast<__half2*>(&g));
    return *reinterpret_cast<uint32_t*>(&r);
}
#define CP_ASYNC16(dst, src) \
    asm volatile("cp.async.cg.shared.global [%0], [%1], 16;" \
                 :: "r"(dst), "l"(src) : "memory")
#define CP_COMMIT() asm volatile("cp.async.commit_group;" ::: "memory")
#define CP_WAIT1()  asm volatile("cp.async.wait_group 1;" ::: "memory")
#define CP_WAIT0()  asm volatile("cp.async.wait_group 0;" ::: "memory")

// ====================== fused pre-pass ======================
constexpr int NT_BLK = Bn * (Cn / 64) * (PIXn / 64);   // 4096
constexpr int NW_ELEM = 9 * On * Cn;                   // 294912
constexpr int NW_BLK = NW_ELEM / (256 * 8);            // 144

__global__ __launch_bounds__(256) void prep_all(const float* __restrict__ x,
                                                const float* __restrict__ w) {
    const int bi = blockIdx.x;
    if (bi < NT_BLK) {
        __shared__ float tile[64][65];
        const int b  = bi / ((Cn / 64) * (PIXn / 64));
        const int r  = bi % ((Cn / 64) * (PIXn / 64));
        const int c0 = (r / (PIXn / 64)) * 64;
        const int p0 = (r % (PIXn / 64)) * 64;
        const int lane = threadIdx.x & 31;
        const int wrp  = threadIdx.x >> 5;     // 0..7
        #pragma unroll
        for (int j = 0; j < 8; j++) {          // warp handles 8 c-rows
            const int c = wrp * 8 + j;
            const float2 v = *reinterpret_cast<const float2*>(
                &x[((size_t)(b * Cn + c0 + c)) * PIXn + p0 + lane * 2]);
            tile[c][lane * 2]     = v.x;
            tile[c][lane * 2 + 1] = v.y;
        }
        __syncthreads();
        #pragma unroll
        for (int j = 0; j < 8; j++) {          // warp handles 8 pixel-rows
            const int p = wrp * 8 + j;
            __half2 v = __floats2half2_rn(tile[lane * 2][p], tile[lane * 2 + 1][p]);
            *reinterpret_cast<__half2*>(
                &g_xh[((size_t)(b * PIXn + p0 + p)) * Cn + c0 + lane * 2]) = v;
        }
    } else {
        const int base = (bi - NT_BLK) * 2048 + threadIdx.x;
        #pragma unroll
        for (int j = 0; j < 8; j++) {
            const int idx = base + j * 256;          // [t][o][c]
            const int c = idx % Cn;
            const int o = (idx / Cn) % On;
            const int t = idx / (Cn * On);
            g_wh[idx] = __float2half_rn(w[((size_t)o * Cn + c) * 9 + t]);
        }
    }
}

// ====================== main kernel ======================
__global__ __launch_bounds__(NTHR, 2) void depthconv_mma(
    const float* __restrict__ depth,
    float* __restrict__ out)
{
    extern __shared__ __align__(16) char smem[];
    const uint32_t sb = smem_u32(smem);
    uint32_t* g_sp = reinterpret_cast<uint32_t*>(smem + OFF_G);  // [9][128] half2

    const int tid = threadIdx.x;     // 0..127
    const int wid = tid >> 5;        // 0..3
    const int lid = tid & 31;

    const int blk = blockIdx.x;          // 0..255
    const int b   = blk >> 5;
    const int tl  = blk & 31;
    const int h0  = (tl >> 2) * 8;       // 8 pixel rows
    const int w0  = (tl & 3) * 16;       // 16 pixel cols

    // ---- gates: 9 taps x 128 pixels, stored as (g,g) half2 ----
    {
        const int hh = h0 + (tid >> 4);
        const int ww = w0 + (tid & 15);
        const float* dptr = depth + b * PIXn;
        const float d0 = dptr[hh * Wn + ww];
        #pragma unroll
        for (int t = 0; t < 9; t++) {
            const int h2 = hh + t / 3 - 1, w2 = ww + t % 3 - 1;
            float g = 0.f;
            if (h2 >= 0 && h2 < Hn && w2 >= 0 && w2 < Wn)
                g = __expf(-ALPHA_F * fabsf(d0 - dptr[h2 * Wn + w2]));
            const __half gh = __float2half_rn(g);
            __half2 gp = __halves2half2(gh, gh);
            g_sp[t * Mt + tid] = *reinterpret_cast<uint32_t*>(&gp);
        }
    }

    // ---- halo staging global offsets (epoch-invariant; smem offs computed) ----
    // 1440 16B-chunks over 128 threads: 11 each, threads<32 do 12.
    const __half* xb = g_xh + (size_t)b * PIXn * Cn;
    int qoff[12];
    #pragma unroll
    for (int j = 0; j < 12; j++) {
        const int i = tid + j * NTHR;
        if (j < 11 || tid < 32) {
            const int ent = i >> 3, seg = i & 7;
            const int hr = ent / 18, hc = ent - hr * 18;
            const int hh = min(max(h0 - 1 + hr, 0), Hn - 1);
            const int ww = min(max(w0 - 1 + hc, 0), Wn - 1);
            qoff[j] = (hh * Wn + ww) * Cn + seg * 8;
        } else qoff[j] = 0;
    }

    auto stage_halo = [&](int e, int buf) {
        const int c0 = e * KC;
        const uint32_t hd = sb + OFF_H + buf * HBUF;
        #pragma unroll
        for (int j = 0; j < 12; j++) {
            if (j < 11 || tid < 32) {
                const int i = tid + j * NTHR;
                const uint32_t so = (uint32_t)((i + (i >> 3)) * 16);
                CP_ASYNC16(hd + so, (const char*)(xb + qoff[j] + c0));
            }
        }
    };
    auto stage_B = [&](int it, int buf) {
        const int e = it / 9, t = it - e * 9;
        const uint32_t bd = sb + OFF_B + buf * BBUF;
        const __half* wsrc = g_wh + (size_t)t * On * Cn + e * KC;
        #pragma unroll
        for (int j = 0; j < 4; j++) {        // 512 chunks / 128 threads
            const int i = tid + j * NTHR;
            const uint32_t so = (uint32_t)((i + (i >> 3)) * 16);
            const int go = (i + 56 * (i >> 3)) * 8;   // o*Cn + seg*8
            CP_ASYNC16(bd + so, (const char*)(wsrc + go));
        }
    };

    // ---- warp tiling: 2 (m) x 2 (n) warps; warp tile 64x32 ----
    const int wm = (wid & 1) * 64;
    const int wn = (wid >> 1) * 32;

    uint32_t abase[4];                    // per-lane A ldmatrix base (tap 0)
    #pragma unroll
    for (int mb = 0; mb < 4; mb++) {
        const int m   = wm + mb * 16 + (lid & 15);
        const int ent = (m >> 4) * 18 + (m & 15);
        abase[mb] = sb + OFF_H + (uint32_t)(ent * HS) * 2 + (uint32_t)(lid >> 4) * 16;
    }
    uint32_t bbase[2];                    // per-lane B ldmatrix base
    {
        const int br = (lid & 7) + ((lid >> 4) << 3);
        const uint32_t bcol = (uint32_t)(((lid >> 3) & 1) << 3) * 2;
        #pragma unroll
        for (int np = 0; np < 2; np++)
            bbase[np] = sb + OFF_B + (uint32_t)((wn + np * 16 + br) * HS) * 2 + bcol;
    }
    const int grow = (lid >> 2);          // gate row within 16-row m-block

    float facc[4][4][4];
    #pragma unroll
    for (int i = 0; i < 4; i++)
        #pragma unroll
        for (int j = 0; j < 4; j++)
            #pragma unroll
            for (int k = 0; k < 4; k++) facc[i][j][k] = 0.f;

    stage_halo(0, 0); stage_B(0, 0); CP_COMMIT();   // group: halo(0)+B(0)
    stage_B(1, 1); CP_COMMIT();                     // group: B(1)

    for (int it = 0; it < NIT; it++) {
        const int e = it / 9, t = it - e * 9;

        if (it >= NIT - 2) { CP_WAIT0(); } else { CP_WAIT1(); }
        __syncthreads();    // staged data (and, first iter, gates) visible

        const int trow = t / 3, tcol = t - trow * 3;
        const uint32_t aoff = (uint32_t)(e & 1) * HBUF
                            + (uint32_t)((trow * 18 + tcol) * (HS * 2));
        const uint32_t boffb = (uint32_t)(it % 3) * BBUF;

        uint32_t g0[4], g1[4];            // (g,g) half2 per fragment row
        #pragma unroll
        for (int mb = 0; mb < 4; mb++) {
            const int r = wm + mb * 16 + grow;
            g0[mb] = g_sp[t * Mt + r];
            g1[mb] = g_sp[t * Mt + r + 8];
        }

        #pragma unroll
        for (int ks = 0; ks < 4; ks++) {
            uint32_t af[4][4];
            #pragma unroll
            for (int mb = 0; mb < 4; mb++) {
                ldsm_x4(af[mb], abase[mb] + aoff + ks * 32);
                af[mb][0] = hmul2u(af[mb][0], g0[mb]);
                af[mb][1] = hmul2u(af[mb][1], g1[mb]);
                af[mb][2] = hmul2u(af[mb][2], g0[mb]);
                af[mb][3] = hmul2u(af[mb][3], g1[mb]);
            }
            uint32_t bf[2][4];
            #pragma unroll
            for (int np = 0; np < 2; np++)
                ldsm_x4(bf[np], bbase[np] + boffb + ks * 32);
            #pragma unroll
            for (int mb = 0; mb < 4; mb++)
                #pragma unroll
                for (int nb = 0; nb < 4; nb++)
                    mma16816(facc[mb][nb], af[mb],
                             bf[nb >> 1][(nb & 1) * 2],
                             bf[nb >> 1][(nb & 1) * 2 + 1]);
        }

        // ---- post-compute spread staging (round-7 pattern) ----
        if (it + 2 < NIT) {
            stage_B(it + 2, (it + 2) % 3);
            if (t == 0 && e + 1 < EPOCHS)
                stage_halo(e + 1, (e + 1) & 1);
            CP_COMMIT();
        }
    }

    // ---- epilogue: D(m=pixel, n=o) -> out[b][o][h][w] ----
    float* ob = out + (size_t)b * On * PIXn;
    const int mrow = wm + (lid >> 2);
    const int ncol = wn + (lid & 3) * 2;
    #pragma unroll
    for (int mb = 0; mb < 4; mb++) {
        #pragma unroll
        for (int half_ = 0; half_ < 2; half_++) {
            const int m  = mrow + mb * 16 + half_ * 8;
            const int hh = h0 + (m >> 4);
            const int ww = w0 + (m & 15);
            const int pix = hh * Wn + ww;
            #pragma unroll
            for (int nb = 0; nb < 4; nb++) {
                const int o = ncol + nb * 8;
                ob[(size_t)o * PIXn + pix]       = facc[mb][nb][half_ * 2];
                ob[(size_t)(o + 1) * PIXn + pix] = facc[mb][nb][half_ * 2 + 1];
            }
        }
    }
}

// ====================== launch ======================
extern "C" void kernel_launch(void* const* d_in, const int* in_sizes, int n_in,
                              void* d_out, int out_size) {
    const float* x     = (const float*)d_in[0];   // (8,512,64,64)
    const float* depth = (const float*)d_in[1];   // (8,1,64,64)
    const float* w     = (const float*)d_in[2];   // (64,512,3,3)
    float* out = (float*)d_out;                   // (8,64,64,64)

    cudaFuncSetAttribute(depthconv_mma,
                         cudaFuncAttributeMaxDynamicSharedMemorySize,
                         SMEM_TOTAL);

    prep_all<<<NT_BLK + NW_BLK, 256>>>(x, w);
    depthconv_mma<<<Bn * 32, NTHR, SMEM_TOTAL>>>(depth, out);
}

// round 10
// speedup vs baseline: 1.4366x; 1.4168x over previous
#include <cuda_runtime.h>
#include <cuda_fp16.h>
#include <cstdint>

// DepthConv: out[b,o,p] = sum_t gate[b,t,p] * sum_c w[t,o,c]*x[b,c,p+shift(t)]
// Round-7 skeleton (best config) with FP16-ACCUMULATE mma (full-rate tensor
// pipe; f32-acc legacy HMMA is half-rate). fp16 accumulation spans only one
// tap x 64-channel chunk (4 mma), then is folded into fp32 with the gate
// applied as FFMA at the fold (no HMUL2 in the A path).

#define ALPHA_F 8.3f

constexpr int Bn = 8;
constexpr int Cn = 512;
constexpr int Hn = 64;
constexpr int Wn = 64;
constexpr int On = 64;
constexpr int PIXn = Hn * Wn;       // 4096

constexpr int Mt = 128;             // pixels per CTA (8 rows x 16 cols)
constexpr int KC = 64;              // c-chunk per epoch
constexpr int EPOCHS = Cn / KC;     // 8
constexpr int NIT = EPOCHS * 9;     // 72 (epoch-major, tap-minor)
constexpr int HE = 180;             // halo entries (10 x 18)
constexpr int HS = 72;              // smem row stride in halves (64 + 8 pad)

// ---- device-global scratch ----
__device__ __half g_xh[(size_t)Bn * PIXn * Cn];   // [b][pixel][c] fp16
__device__ __half g_wh[9 * On * Cn];              // [tap][o][c]  fp16

// ---- smem layout (bytes) ----
constexpr int HBUF = HE * HS * 2;            // 25920 (x2 buffers)
constexpr int BBUF = On * HS * 2;            // 9216  (x3 buffers)
constexpr int OFF_H = 0;
constexpr int OFF_B = 2 * HBUF;              // 51840
constexpr int OFF_G = OFF_B + 3 * BBUF;      // 79488 gates 9*128*4 (float)
constexpr int SMEM_TOTAL = OFF_G + 9 * Mt * 4;  // 84096 -> 2 CTAs/SM

// ====================== helpers ======================
__device__ __forceinline__ uint32_t smem_u32(const void* p) {
    uint32_t a;
    asm("{ .reg .u64 t; cvta.to.shared.u64 t, %1; cvt.u32.u64 %0, t; }"
        : "=r"(a) : "l"(p));
    return a;
}
__device__ __forceinline__ void ldsm_x4(uint32_t* r, uint32_t addr) {
    asm volatile("ldmatrix.sync.aligned.m8n8.x4.shared.b16 {%0,%1,%2,%3}, [%4];"
        : "=r"(r[0]), "=r"(r[1]), "=r"(r[2]), "=r"(r[3]) : "r"(addr));
}
// fp16-accumulate mma: D,C are 2 b32 regs (4 halves)
__device__ __forceinline__ void mma16816h(uint32_t* c, const uint32_t* a,
                                          uint32_t b0, uint32_t b1) {
    asm volatile(
        "mma.sync.aligned.m16n8k16.row.col.f16.f16.f16.f16 "
        "{%0,%1}, {%2,%3,%4,%5}, {%6,%7}, {%0,%1};"
        : "+r"(c[0]), "+r"(c[1])
        : "r"(a[0]), "r"(a[1]), "r"(a[2]), "r"(a[3]), "r"(b0), "r"(b1));
}
#define CP_ASYNC16(dst, src) \
    asm volatile("cp.async.cg.shared.global [%0], [%1], 16;" \
                 :: "r"(dst), "l"(src) : "memory")
#define CP_COMMIT() asm volatile("cp.async.commit_group;" ::: "memory")
#define CP_WAIT1()  asm volatile("cp.async.wait_group 1;" ::: "memory")
#define CP_WAIT0()  asm volatile("cp.async.wait_group 0;" ::: "memory")

// ====================== fused pre-pass ======================
constexpr int NT_BLK = Bn * (Cn / 64) * (PIXn / 64);   // 4096
constexpr int NW_ELEM = 9 * On * Cn;                   // 294912
constexpr int NW_BLK = NW_ELEM / (256 * 8);            // 144

__global__ __launch_bounds__(256) void prep_all(const float* __restrict__ x,
                                                const float* __restrict__ w) {
    const int bi = blockIdx.x;
    if (bi < NT_BLK) {
        __shared__ float tile[64][65];
        const int b  = bi / ((Cn / 64) * (PIXn / 64));
        const int r  = bi % ((Cn / 64) * (PIXn / 64));
        const int c0 = (r / (PIXn / 64)) * 64;
        const int p0 = (r % (PIXn / 64)) * 64;
        const int lane = threadIdx.x & 31;
        const int wrp  = threadIdx.x >> 5;     // 0..7
        #pragma unroll
        for (int j = 0; j < 8; j++) {          // warp handles 8 c-rows
            const int c = wrp * 8 + j;
            const float2 v = *reinterpret_cast<const float2*>(
                &x[((size_t)(b * Cn + c0 + c)) * PIXn + p0 + lane * 2]);
            tile[c][lane * 2]     = v.x;
            tile[c][lane * 2 + 1] = v.y;
        }
        __syncthreads();
        #pragma unroll
        for (int j = 0; j < 8; j++) {          // warp handles 8 pixel-rows
            const int p = wrp * 8 + j;
            __half2 v = __floats2half2_rn(tile[lane * 2][p], tile[lane * 2 + 1][p]);
            *reinterpret_cast<__half2*>(
                &g_xh[((size_t)(b * PIXn + p0 + p)) * Cn + c0 + lane * 2]) = v;
        }
    } else {
        const int base = (bi - NT_BLK) * 2048 + threadIdx.x;
        #pragma unroll
        for (int j = 0; j < 8; j++) {
            const int idx = base + j * 256;          // [t][o][c]
            const int c = idx % Cn;
            const int o = (idx / Cn) % On;
            const int t = idx / (Cn * On);
            g_wh[idx] = __float2half_rn(w[((size_t)o * Cn + c) * 9 + t]);
        }
    }
}

// ====================== main kernel ======================
__global__ __launch_bounds__(256, 2) void depthconv_mma(
    const float* __restrict__ depth,
    float* __restrict__ out)
{
    extern __shared__ __align__(16) char smem[];
    const uint32_t sb = smem_u32(smem);
    float* g_sf = reinterpret_cast<float*>(smem + OFF_G);   // [9][128] float

    const int tid = threadIdx.x;
    const int wid = tid >> 5;
    const int lid = tid & 31;

    const int blk = blockIdx.x;          // 0..255
    const int b   = blk >> 5;
    const int tl  = blk & 31;
    const int h0  = (tl >> 2) * 8;       // 8 pixel rows
    const int w0  = (tl & 3) * 16;       // 16 pixel cols

    // ---- gates: 9 taps x 128 pixels (fp32) ----
    if (tid < Mt) {
        const int hh = h0 + (tid >> 4);
        const int ww = w0 + (tid & 15);
        const float* dptr = depth + b * PIXn;
        const float d0 = dptr[hh * Wn + ww];
        #pragma unroll
        for (int t = 0; t < 9; t++) {
            const int h2 = hh + t / 3 - 1, w2 = ww + t % 3 - 1;
            float g = 0.f;
            if (h2 >= 0 && h2 < Hn && w2 >= 0 && w2 < Wn)
                g = __expf(-ALPHA_F * fabsf(d0 - dptr[h2 * Wn + w2]));
            g_sf[t * Mt + tid] = g;
        }
    }

    // ---- halo staging slots (epoch-invariant addressing) ----
    const __half* xb = g_xh + (size_t)b * PIXn * Cn;
    const int nj = (tid < 160) ? 6 : 5;   // 1440 chunks over 256 threads
    int qoff[6];        // global half offset (add c0)
    uint32_t soff[6];   // smem byte offset within halo buffer
    #pragma unroll
    for (int j = 0; j < 6; j++) {
        const int i = tid + j * 256;
        const int ent = i >> 3, seg = i & 7;
        const int hr = ent / 18, hc = ent - hr * 18;
        const int hh = min(max(h0 - 1 + hr, 0), Hn - 1);
        const int ww = min(max(w0 - 1 + hc, 0), Wn - 1);
        qoff[j] = (hh * Wn + ww) * Cn + seg * 8;
        soff[j] = (uint32_t)(ent * HS + seg * 8) * 2;
    }
    // B staging: 64 rows x 8 segs = 512 chunks -> 2 per thread
    uint32_t bsoff[2];
    int boff[2];
    #pragma unroll
    for (int j = 0; j < 2; j++) {
        const int i = tid + j * 256;
        const int o = i >> 3, seg = i & 7;
        boff[j]  = o * Cn + seg * 8;              // add tap*On*Cn + c0
        bsoff[j] = (uint32_t)(o * HS + seg * 8) * 2;
    }

    auto stage_halo = [&](int e, int buf) {
        const int c0 = e * KC;
        const uint32_t hd = sb + OFF_H + buf * HBUF;
        #pragma unroll
        for (int j = 0; j < 6; j++)
            if (j < nj)
                CP_ASYNC16(hd + soff[j], (const char*)(xb + qoff[j] + c0));
    };
    auto stage_B = [&](int it, int buf) {
        const int e = it / 9, t = it - e * 9;
        const uint32_t bd = sb + OFF_B + buf * BBUF;
        const __half* wsrc = g_wh + (size_t)t * On * Cn + e * KC;
        #pragma unroll
        for (int j = 0; j < 2; j++)
            CP_ASYNC16(bd + bsoff[j], (const char*)(wsrc + boff[j]));
    };

    // ---- warp tiling: 4 (m) x 2 (n) warps; warp tile 32x32 ----
    const int wm = (wid & 3) * 32;
    const int wn = (wid >> 2) * 32;

    uint32_t abase[2];                    // per-lane A ldmatrix base (tap 0)
    #pragma unroll
    for (int mb = 0; mb < 2; mb++) {
        const int m   = wm + mb * 16 + (lid & 15);
        const int ent = (m >> 4) * 18 + (m & 15);
        abase[mb] = sb + OFF_H + (uint32_t)(ent * HS) * 2 + (uint32_t)(lid >> 4) * 16;
    }
    uint32_t bbase[2];                    // per-lane B ldmatrix base
    {
        const int br = (lid & 7) + ((lid >> 4) << 3);
        const uint32_t bcol = (uint32_t)(((lid >> 3) & 1) << 3) * 2;
        #pragma unroll
        for (int np = 0; np < 2; np++)
            bbase[np] = sb + OFF_B + (uint32_t)((wn + np * 16 + br) * HS) * 2 + bcol;
    }
    const int grow = (lid >> 2);          // accumulator row within m-block

    float facc[2][4][4];
    #pragma unroll
    for (int i = 0; i < 2; i++)
        #pragma unroll
        for (int j = 0; j < 4; j++)
            #pragma unroll
            for (int k = 0; k < 4; k++) facc[i][j][k] = 0.f;

    stage_halo(0, 0); stage_B(0, 0); CP_COMMIT();   // group: halo(0)+B(0)
    stage_B(1, 1); CP_COMMIT();                     // group: B(1)

    for (int it = 0; it < NIT; it++) {
        const int e = it / 9, t = it - e * 9;

        if (it >= NIT - 2) { CP_WAIT0(); } else { CP_WAIT1(); }
        __syncthreads();    // staged data (and, first iter, gates) visible

        const int trow = t / 3, tcol = t - trow * 3;
        const uint32_t aoff = (uint32_t)(e & 1) * HBUF
                            + (uint32_t)((trow * 18 + tcol) * (HS * 2));
        const uint32_t boffb = (uint32_t)(it % 3) * BBUF;

        // fp16 accumulators for this (tap, c-chunk): 2 regs per 16x8 tile
        uint32_t hacc[2][4][2];
        #pragma unroll
        for (int mb = 0; mb < 2; mb++)
            #pragma unroll
            for (int nb = 0; nb < 4; nb++)
                hacc[mb][nb][0] = hacc[mb][nb][1] = 0u;

        #pragma unroll
        for (int ks = 0; ks < 4; ks++) {
            uint32_t af[2][4];
            #pragma unroll
            for (int mb = 0; mb < 2; mb++)
                ldsm_x4(af[mb], abase[mb] + aoff + ks * 32);
            uint32_t bf[2][4];
            #pragma unroll
            for (int np = 0; np < 2; np++)
                ldsm_x4(bf[np], bbase[np] + boffb + ks * 32);
            #pragma unroll
            for (int mb = 0; mb < 2; mb++)
                #pragma unroll
                for (int nb = 0; nb < 4; nb++)
                    mma16816h(hacc[mb][nb], af[mb],
                              bf[nb >> 1][(nb & 1) * 2],
                              bf[nb >> 1][(nb & 1) * 2 + 1]);
        }

        // ---- post-compute spread staging (round-7 pattern) ----
        if (it + 2 < NIT) {
            stage_B(it + 2, (it + 2) % 3);
            if (t == 0 && e + 1 < EPOCHS)
                stage_halo(e + 1, (e + 1) & 1);
            CP_COMMIT();
        }

        // ---- fold fp16 chunk sums into fp32 with the gate (FFMA) ----
        #pragma unroll
        for (int mb = 0; mb < 2; mb++) {
            const int r = wm + mb * 16 + grow;
            const float ga = g_sf[t * Mt + r];
            const float gb = g_sf[t * Mt + r + 8];
            #pragma unroll
            for (int nb = 0; nb < 4; nb++) {
                const float2 lo = __half22float2(
                    *reinterpret_cast<__half2*>(&hacc[mb][nb][0]));
                const float2 hi = __half22float2(
                    *reinterpret_cast<__half2*>(&hacc[mb][nb][1]));
                facc[mb][nb][0] += ga * lo.x;
                facc[mb][nb][1] += ga * lo.y;
                facc[mb][nb][2] += gb * hi.x;
                facc[mb][nb][3] += gb * hi.y;
            }
        }
    }

    // ---- epilogue: D(m=pixel, n=o) -> out[b][o][h][w] ----
    float* ob = out + (size_t)b * On * PIXn;
    const int mrow = wm + (lid >> 2);
    const int ncol = wn + (lid & 3) * 2;
    #pragma unroll
    for (int mb = 0; mb < 2; mb++) {
        #pragma unroll
        for (int half_ = 0; half_ < 2; half_++) {
            const int m  = mrow + mb * 16 + half_ * 8;
            const int hh = h0 + (m >> 4);
            const int ww = w0 + (m & 15);
            const int pix = hh * Wn + ww;
            #pragma unroll
            for (int nb = 0; nb < 4; nb++) {
                const int o = ncol + nb * 8;
                ob[(size_t)o * PIXn + pix]       = facc[mb][nb][half_ * 2];
                ob[(size_t)(o + 1) * PIXn + pix] = facc[mb][nb][half_ * 2 + 1];
            }
        }
    }
}

// ====================== launch ======================
extern "C" void kernel_launch(void* const* d_in, const int* in_sizes, int n_in,
                              void* d_out, int out_size) {
    const float* x     = (const float*)d_in[0];   // (8,512,64,64)
    const float* depth = (const float*)d_in[1];   // (8,1,64,64)
    const float* w     = (const float*)d_in[2];   // (64,512,3,3)
    float* out = (float*)d_out;                   // (8,64,64,64)

    cudaFuncSetAttribute(depthconv_mma,
                         cudaFuncAttributeMaxDynamicSharedMemorySize,
                         SMEM_TOTAL);

    prep_all<<<NT_BLK + NW_BLK, 256>>>(x, w);
    depthconv_mma<<<Bn * 32, 256, SMEM_TOTAL>>>(depth, out);
}